// round 13
// baseline (speedup 1.0000x reference)
#include <cuda_runtime.h>
#include <cuda_fp16.h>
#include <stdint.h>

#define NUM_SEGMENTS 4480
#define ATOM_DIM 64
#define BOND_DIM 16
#define N_EDGES 65536
#define YSTRIDE 1152   // padded row stride (halves): 1024 kernel cols + 64 bias + 64 pad

// Scratch: per-atom projected features in fp16, padded stride.
__device__ __half g_Yh[(size_t)NUM_SEGMENTS * YSTRIDE];

// ---- tensor-core helpers ----
__device__ __forceinline__ uint32_t smem_u32(const void* p) {
    return (uint32_t)__cvta_generic_to_shared(p);
}
__device__ __forceinline__ void ldm_x4(uint32_t& r0, uint32_t& r1,
                                       uint32_t& r2, uint32_t& r3, uint32_t addr) {
    asm volatile("ldmatrix.sync.aligned.m8n8.x4.shared.b16 {%0,%1,%2,%3}, [%4];"
                 : "=r"(r0), "=r"(r1), "=r"(r2), "=r"(r3) : "r"(addr));
}
__device__ __forceinline__ void mma16816(float* c,
                                         uint32_t a0, uint32_t a1, uint32_t a2, uint32_t a3,
                                         uint32_t b0, uint32_t b1) {
    asm volatile("mma.sync.aligned.m16n8k16.row.col.f32.f16.f16.f32 "
                 "{%0,%1,%2,%3}, {%4,%5,%6,%7}, {%8,%9}, {%0,%1,%2,%3};"
                 : "+f"(c[0]), "+f"(c[1]), "+f"(c[2]), "+f"(c[3])
                 : "r"(a0), "r"(a1), "r"(a2), "r"(a3), "r"(b0), "r"(b1));
}

#define AH_STRIDE 72
#define BS_STRIDE 72

// ---------------------------------------------------------------------------
// Phase 1 (tensor cores): Y = atom (4480x64) @ W (64x1088) -> fp16 (stride 1152).
// R12-validated. Tile 64(M) x 128(N), grid (70, 9). y==0 blocks zero `out`.
// ---------------------------------------------------------------------------
__global__ void __launch_bounds__(256)
proj_kernel(const float* __restrict__ atom,
            const float* __restrict__ kern,
            const float* __restrict__ bias,
            float* __restrict__ out)
{
    __shared__ __align__(16) __half Ah[64 * AH_STRIDE];    // 9 KB
    __shared__ __align__(16) __half Bs[128 * BS_STRIDE];   // 18 KB

    const int a0  = blockIdx.x * 64;    // 70 blocks
    const int c0g = blockIdx.y * 128;   // 9 blocks (last: 1024..1151, tail padded)
    const int tid = threadIdx.x;

    if (blockIdx.y == 0) {
        float4* oz = (float4*)(out + (size_t)a0 * 64);
        #pragma unroll
        for (int t = 0; t < 4; t++)
            oz[tid + t * 256] = make_float4(0.f, 0.f, 0.f, 0.f);
    }

    #pragma unroll
    for (int t = 0; t < 4; t++) {
        int idx = tid + t * 256;
        int r = idx >> 4, f4 = idx & 15;
        float4 v = *(const float4*)(atom + (size_t)(a0 + r) * 64 + f4 * 4);
        __half2 h01 = __floats2half2_rn(v.x, v.y);
        __half2 h23 = __floats2half2_rn(v.z, v.w);
        *(uint2*)&Ah[r * AH_STRIDE + f4 * 4] =
            make_uint2(*(uint32_t*)&h01, *(uint32_t*)&h23);
    }
    #pragma unroll
    for (int t = 0; t < 8; t++) {
        int idx = tid + t * 256;
        int c = idx >> 4, f4 = idx & 15;
        int gc = c0g + c;
        float4 v = make_float4(0.f, 0.f, 0.f, 0.f);
        if (gc < 1024) {
            int kk = gc >> 6, i = gc & 63;
            v = *(const float4*)(kern + kk * 4096 + i * 64 + f4 * 4);
        } else if (gc < 1088) {
            v = *(const float4*)(bias + (gc - 1024) * 64 + f4 * 4);
        }
        __half2 h01 = __floats2half2_rn(v.x, v.y);
        __half2 h23 = __floats2half2_rn(v.z, v.w);
        *(uint2*)&Bs[c * BS_STRIDE + f4 * 4] =
            make_uint2(*(uint32_t*)&h01, *(uint32_t*)&h23);
    }
    __syncthreads();

    const int wid  = tid >> 5;
    const int lane = tid & 31;
    const int m0   = (wid & 3) * 16;   // row group
    const int ch   = wid >> 2;         // col half (0 or 1)

    uint32_t Af[4][4];
    {
        const uint32_t a_base =
            smem_u32(&Ah[(m0 + (lane & 15)) * AH_STRIDE + ((lane >> 4) << 3)]);
        #pragma unroll
        for (int ks = 0; ks < 4; ks++)
            ldm_x4(Af[ks][0], Af[ks][1], Af[ks][2], Af[ks][3], a_base + ks * 32);
    }

    const uint32_t b_base =
        smem_u32(&Bs[(ch * 64 + ((lane >> 4) << 3) + (lane & 7)) * BS_STRIDE +
                     (((lane >> 3) & 1) << 3)]);

    float acc[8][4] = {};
    #pragma unroll
    for (int ks = 0; ks < 4; ks++) {
        #pragma unroll
        for (int nss = 0; nss < 4; nss++) {
            uint32_t B0, B1, B2, B3;
            ldm_x4(B0, B1, B2, B3,
                   b_base + nss * 16 * BS_STRIDE * 2 + ks * 32);
            mma16816(acc[2 * nss],     Af[ks][0], Af[ks][1], Af[ks][2], Af[ks][3], B0, B1);
            mma16816(acc[2 * nss + 1], Af[ks][0], Af[ks][1], Af[ks][2], Af[ks][3], B2, B3);
        }
    }

    const int r  = lane >> 2;
    const int cp = (lane & 3) * 2;
    const int colbase = c0g + ch * 64;
    #pragma unroll
    for (int s = 0; s < 8; s++) {
        const int col = colbase + s * 8 + cp;
        const size_t row0 = (size_t)(a0 + m0 + r);
        *(__half2*)&g_Yh[row0 * YSTRIDE + col]       = __floats2half2_rn(acc[s][0], acc[s][1]);
        *(__half2*)&g_Yh[(row0 + 8) * YSTRIDE + col] = __floats2half2_rn(acc[s][2], acc[s][3]);
    }
}

// ---------------------------------------------------------------------------
// Phase 2: half-warp per edge; ALL loads hoisted into registers (MLP ~21)
// before any math. launch_bounds(256,3) -> <=85 regs so nothing spills and
// the load batch stays fully in flight.
// ---------------------------------------------------------------------------
__global__ void __launch_bounds__(256, 3)
edge_kernel(const float* __restrict__ bond,
            const int* __restrict__ pair,
            float* __restrict__ out)
{
    const int warp = blockIdx.x * 8 + (threadIdx.x >> 5);
    const int half = (threadIdx.x >> 4) & 1;
    const int lid  = threadIdx.x & 15;
    const int e = warp * 2 + half;

    const int2 pr = ((const int2*)pair)[e];
    const int dst = pr.x;
    const int src = pr.y;

    const __half* __restrict__ y = g_Yh + (size_t)src * YSTRIDE + 4 * lid;
    const float4* __restrict__ bp = (const float4*)(bond + (size_t)e * 16);

    // ---- front-batched loads: 17 x LDG.64 (Y) + 4 x LDG.128 (bond) ----
    uint2 v[17];
    #pragma unroll
    for (int k = 0; k < 16; k++) v[k] = *(const uint2*)(y + k * 64);
    v[16] = *(const uint2*)(y + 1024);

    const float4 q0 = __ldg(bp + 0);
    const float4 q1 = __ldg(bp + 1);
    const float4 q2 = __ldg(bp + 2);
    const float4 q3 = __ldg(bp + 3);
    const float bk[16] = {q0.x, q0.y, q0.z, q0.w,
                          q1.x, q1.y, q1.z, q1.w,
                          q2.x, q2.y, q2.z, q2.w,
                          q3.x, q3.y, q3.z, q3.w};

    // ---- math ----
    float m0, m1, m2, m3;
    {
        const float2 flo = __half22float2(*(const __half2*)&v[16].x);
        const float2 fhi = __half22float2(*(const __half2*)&v[16].y);
        m0 = flo.x; m1 = flo.y; m2 = fhi.x; m3 = fhi.y;
    }
    #pragma unroll
    for (int k = 0; k < 16; k++) {
        const float2 flo = __half22float2(*(const __half2*)&v[k].x);
        const float2 fhi = __half22float2(*(const __half2*)&v[k].y);
        const float b = bk[k];
        m0 = fmaf(b, flo.x, m0);
        m1 = fmaf(b, flo.y, m1);
        m2 = fmaf(b, fhi.x, m2);
        m3 = fmaf(b, fhi.y, m3);
    }

    float* o = out + (size_t)dst * 64 + 4 * lid;
    asm volatile("red.global.add.v4.f32 [%0], {%1, %2, %3, %4};"
                 :: "l"(o), "f"(m0), "f"(m1), "f"(m2), "f"(m3)
                 : "memory");
}

extern "C" void kernel_launch(void* const* d_in, const int* in_sizes, int n_in,
                              void* d_out, int out_size)
{
    const float* atom = (const float*)d_in[0];      // [4480, 64]
    const float* bond = (const float*)d_in[1];      // [65536, 16]
    const int*   pair = (const int*)d_in[2];        // [65536, 2] int32
    const float* kern = (const float*)d_in[3];      // [16, 4096]
    const float* bias = (const float*)d_in[4];      // [4096]
    float*       out  = (float*)d_out;              // [4480, 64]

    (void)in_sizes; (void)n_in; (void)out_size;

    dim3 grid1(NUM_SEGMENTS / 64, 9);  // (70, 9); y==0 blocks zero `out`
    proj_kernel<<<grid1, 256>>>(atom, kern, bias, out);

    edge_kernel<<<N_EDGES / 16, 256>>>(bond, pair, out);
}

// round 15
// speedup vs baseline: 1.0965x; 1.0965x over previous
#include <cuda_runtime.h>
#include <cuda_fp16.h>
#include <stdint.h>

#define NUM_SEGMENTS 4480
#define ATOM_DIM 64
#define BOND_DIM 16
#define N_EDGES 65536
#define YSTRIDE 1152   // padded row stride (halves): 1024 kernel cols + 64 bias + 64 pad

// Scratch: per-atom projected features in fp16, padded stride.
__device__ __half g_Yh[(size_t)NUM_SEGMENTS * YSTRIDE];

// ---- tensor-core helpers ----
__device__ __forceinline__ uint32_t smem_u32(const void* p) {
    return (uint32_t)__cvta_generic_to_shared(p);
}
__device__ __forceinline__ void ldm_x4(uint32_t& r0, uint32_t& r1,
                                       uint32_t& r2, uint32_t& r3, uint32_t addr) {
    asm volatile("ldmatrix.sync.aligned.m8n8.x4.shared.b16 {%0,%1,%2,%3}, [%4];"
                 : "=r"(r0), "=r"(r1), "=r"(r2), "=r"(r3) : "r"(addr));
}
__device__ __forceinline__ void mma16816(float* c,
                                         uint32_t a0, uint32_t a1, uint32_t a2, uint32_t a3,
                                         uint32_t b0, uint32_t b1) {
    asm volatile("mma.sync.aligned.m16n8k16.row.col.f32.f16.f16.f32 "
                 "{%0,%1,%2,%3}, {%4,%5,%6,%7}, {%8,%9}, {%0,%1,%2,%3};"
                 : "+f"(c[0]), "+f"(c[1]), "+f"(c[2]), "+f"(c[3])
                 : "r"(a0), "r"(a1), "r"(a2), "r"(a3), "r"(b0), "r"(b1));
}

#define AH_STRIDE 72
#define BS_STRIDE 72
#define SG_STRIDE 136   // halves; 272 B per row = 17 x 16 B -> uint4-aligned every row

// ---------------------------------------------------------------------------
// Phase 1 (tensor cores): Y = atom (4480x64) @ W (64x1088) -> fp16 (stride 1152).
// Tile 64(M) x 128(N), grid (70, 9). y==0 blocks zero `out`.
// Epilogue stages the 64x128 tile in smem, then stores coalesced STG.128.
// ---------------------------------------------------------------------------
__global__ void __launch_bounds__(256)
proj_kernel(const float* __restrict__ atom,
            const float* __restrict__ kern,
            const float* __restrict__ bias,
            float* __restrict__ out)
{
    __shared__ __align__(16) __half Ah[64 * AH_STRIDE];     // 9 KB
    __shared__ __align__(16) __half Bs[128 * BS_STRIDE];    // 18 KB
    __shared__ __align__(16) __half Sg[64 * SG_STRIDE];     // 17 KB staging

    const int a0  = blockIdx.x * 64;    // 70 blocks
    const int c0g = blockIdx.y * 128;   // 9 blocks (last: 1024..1151, tail padded)
    const int tid = threadIdx.x;

    if (blockIdx.y == 0) {
        float4* oz = (float4*)(out + (size_t)a0 * 64);
        #pragma unroll
        for (int t = 0; t < 4; t++)
            oz[tid + t * 256] = make_float4(0.f, 0.f, 0.f, 0.f);
    }

    // Fill Ah[r][j] (fp32 -> fp16), float4 loads
    #pragma unroll
    for (int t = 0; t < 4; t++) {
        int idx = tid + t * 256;
        int r = idx >> 4, f4 = idx & 15;
        float4 v = *(const float4*)(atom + (size_t)(a0 + r) * 64 + f4 * 4);
        __half2 h01 = __floats2half2_rn(v.x, v.y);
        __half2 h23 = __floats2half2_rn(v.z, v.w);
        *(uint2*)&Ah[r * AH_STRIDE + f4 * 4] =
            make_uint2(*(uint32_t*)&h01, *(uint32_t*)&h23);
    }
    // Fill Bs[c][j] = W[j][c0g+c]
    #pragma unroll
    for (int t = 0; t < 8; t++) {
        int idx = tid + t * 256;
        int c = idx >> 4, f4 = idx & 15;
        int gc = c0g + c;
        float4 v = make_float4(0.f, 0.f, 0.f, 0.f);
        if (gc < 1024) {
            int kk = gc >> 6, i = gc & 63;
            v = *(const float4*)(kern + kk * 4096 + i * 64 + f4 * 4);
        } else if (gc < 1088) {
            v = *(const float4*)(bias + (gc - 1024) * 64 + f4 * 4);
        }
        __half2 h01 = __floats2half2_rn(v.x, v.y);
        __half2 h23 = __floats2half2_rn(v.z, v.w);
        *(uint2*)&Bs[c * BS_STRIDE + f4 * 4] =
            make_uint2(*(uint32_t*)&h01, *(uint32_t*)&h23);
    }
    __syncthreads();

    const int wid  = tid >> 5;
    const int lane = tid & 31;
    const int m0   = (wid & 3) * 16;   // row group
    const int ch   = wid >> 2;         // col half (0 or 1)

    uint32_t Af[4][4];
    {
        const uint32_t a_base =
            smem_u32(&Ah[(m0 + (lane & 15)) * AH_STRIDE + ((lane >> 4) << 3)]);
        #pragma unroll
        for (int ks = 0; ks < 4; ks++)
            ldm_x4(Af[ks][0], Af[ks][1], Af[ks][2], Af[ks][3], a_base + ks * 32);
    }

    const uint32_t b_base =
        smem_u32(&Bs[(ch * 64 + ((lane >> 4) << 3) + (lane & 7)) * BS_STRIDE +
                     (((lane >> 3) & 1) << 3)]);

    float acc[8][4] = {};
    #pragma unroll
    for (int ks = 0; ks < 4; ks++) {
        #pragma unroll
        for (int nss = 0; nss < 4; nss++) {
            uint32_t B0, B1, B2, B3;
            ldm_x4(B0, B1, B2, B3,
                   b_base + nss * 16 * BS_STRIDE * 2 + ks * 32);
            mma16816(acc[2 * nss],     Af[ks][0], Af[ks][1], Af[ks][2], Af[ks][3], B0, B1);
            mma16816(acc[2 * nss + 1], Af[ks][0], Af[ks][1], Af[ks][2], Af[ks][3], B2, B3);
        }
    }

    // Stage accumulators in smem (local cols within this block's 128-col tile)
    const int r  = lane >> 2;
    const int cp = (lane & 3) * 2;
    #pragma unroll
    for (int s = 0; s < 8; s++) {
        const int lc = ch * 64 + s * 8 + cp;            // local col 0..127
        *(__half2*)&Sg[(m0 + r) * SG_STRIDE + lc]     = __floats2half2_rn(acc[s][0], acc[s][1]);
        *(__half2*)&Sg[(m0 + r + 8) * SG_STRIDE + lc] = __floats2half2_rn(acc[s][2], acc[s][3]);
    }
    __syncthreads();

    // Coalesced copy: 64 rows x 128 halves = 1024 uint4; 16 threads per row.
    #pragma unroll
    for (int t = 0; t < 4; t++) {
        int idx = tid + t * 256;
        int row = idx >> 4, ck = idx & 15;      // ck: 16B chunk (8 halves)
        uint4 v = *(const uint4*)&Sg[row * SG_STRIDE + ck * 8];
        *(uint4*)&g_Yh[(size_t)(a0 + row) * YSTRIDE + c0g + ck * 8] = v;
    }
}

// ---------------------------------------------------------------------------
// Phase 2: half-warp per edge (exact R12 structure — validated 13.7us).
// Lane lid handles output features 4*lid..4*lid+3.
// ---------------------------------------------------------------------------
__global__ void __launch_bounds__(256)
edge_kernel(const float* __restrict__ bond,
            const int* __restrict__ pair,
            float* __restrict__ out)
{
    const int warp = blockIdx.x * 8 + (threadIdx.x >> 5);
    const int half = (threadIdx.x >> 4) & 1;
    const int lid  = threadIdx.x & 15;
    const int e = warp * 2 + half;

    const int2 pr = ((const int2*)pair)[e];
    const int dst = pr.x;
    const int src = pr.y;

    const float4* __restrict__ bp = (const float4*)(bond + (size_t)e * 16);
    const float4 q0 = __ldg(bp + 0);
    const float4 q1 = __ldg(bp + 1);
    const float4 q2 = __ldg(bp + 2);
    const float4 q3 = __ldg(bp + 3);
    const float bk[16] = {q0.x, q0.y, q0.z, q0.w,
                          q1.x, q1.y, q1.z, q1.w,
                          q2.x, q2.y, q2.z, q2.w,
                          q3.x, q3.y, q3.z, q3.w};

    const __half* __restrict__ y = g_Yh + (size_t)src * YSTRIDE + 4 * lid;

    float m0, m1, m2, m3;
    {
        const uint2 v = *(const uint2*)(y + 1024);
        const float2 flo = __half22float2(*(const __half2*)&v.x);
        const float2 fhi = __half22float2(*(const __half2*)&v.y);
        m0 = flo.x; m1 = flo.y; m2 = fhi.x; m3 = fhi.y;
    }

    #pragma unroll
    for (int k = 0; k < 16; k++) {
        const uint2 v = *(const uint2*)(y + k * 64);
        const float2 flo = __half22float2(*(const __half2*)&v.x);
        const float2 fhi = __half22float2(*(const __half2*)&v.y);
        const float b = bk[k];
        m0 = fmaf(b, flo.x, m0);
        m1 = fmaf(b, flo.y, m1);
        m2 = fmaf(b, fhi.x, m2);
        m3 = fmaf(b, fhi.y, m3);
    }

    float* o = out + (size_t)dst * 64 + 4 * lid;
    asm volatile("red.global.add.v4.f32 [%0], {%1, %2, %3, %4};"
                 :: "l"(o), "f"(m0), "f"(m1), "f"(m2), "f"(m3)
                 : "memory");
}

extern "C" void kernel_launch(void* const* d_in, const int* in_sizes, int n_in,
                              void* d_out, int out_size)
{
    const float* atom = (const float*)d_in[0];      // [4480, 64]
    const float* bond = (const float*)d_in[1];      // [65536, 16]
    const int*   pair = (const int*)d_in[2];        // [65536, 2] int32
    const float* kern = (const float*)d_in[3];      // [16, 4096]
    const float* bias = (const float*)d_in[4];      // [4096]
    float*       out  = (float*)d_out;              // [4480, 64]

    (void)in_sizes; (void)n_in; (void)out_size;

    dim3 grid1(NUM_SEGMENTS / 64, 9);  // (70, 9); y==0 blocks zero `out`
    proj_kernel<<<grid1, 256>>>(atom, kern, bias, out);

    edge_kernel<<<N_EDGES / 16, 256>>>(bond, pair, out);
}

// round 16
// speedup vs baseline: 1.1099x; 1.0122x over previous
#include <cuda_runtime.h>
#include <cuda_fp16.h>
#include <stdint.h>

#define NUM_SEGMENTS 4480
#define ATOM_DIM 64
#define BOND_DIM 16
#define N_EDGES 65536
#define YSTRIDE 1152   // padded row stride (halves): 1024 kernel cols + 64 bias + 64 pad

// Scratch: per-atom projected features in fp16, padded stride.
__device__ __half g_Yh[(size_t)NUM_SEGMENTS * YSTRIDE];

// ---- tensor-core helpers ----
__device__ __forceinline__ uint32_t smem_u32(const void* p) {
    return (uint32_t)__cvta_generic_to_shared(p);
}
__device__ __forceinline__ void ldm_x4(uint32_t& r0, uint32_t& r1,
                                       uint32_t& r2, uint32_t& r3, uint32_t addr) {
    asm volatile("ldmatrix.sync.aligned.m8n8.x4.shared.b16 {%0,%1,%2,%3}, [%4];"
                 : "=r"(r0), "=r"(r1), "=r"(r2), "=r"(r3) : "r"(addr));
}
__device__ __forceinline__ void mma16816(float* c,
                                         uint32_t a0, uint32_t a1, uint32_t a2, uint32_t a3,
                                         uint32_t b0, uint32_t b1) {
    asm volatile("mma.sync.aligned.m16n8k16.row.col.f32.f16.f16.f32 "
                 "{%0,%1,%2,%3}, {%4,%5,%6,%7}, {%8,%9}, {%0,%1,%2,%3};"
                 : "+f"(c[0]), "+f"(c[1]), "+f"(c[2]), "+f"(c[3])
                 : "r"(a0), "r"(a1), "r"(a2), "r"(a3), "r"(b0), "r"(b1));
}

#define AH_STRIDE 72
#define BS_STRIDE 72
#define SG_STRIDE 136   // halves; 272 B per row = 17 x 16 B -> uint4-aligned every row

// ---------------------------------------------------------------------------
// Phase 1 (tensor cores): Y = atom (4480x64) @ W (64x1088) -> fp16 (stride 1152).
// R15-validated body + PDL trigger at the end.
// ---------------------------------------------------------------------------
__global__ void __launch_bounds__(256)
proj_kernel(const float* __restrict__ atom,
            const float* __restrict__ kern,
            const float* __restrict__ bias,
            float* __restrict__ out)
{
    __shared__ __align__(16) __half Ah[64 * AH_STRIDE];     // 9 KB
    __shared__ __align__(16) __half Bs[128 * BS_STRIDE];    // 18 KB
    __shared__ __align__(16) __half Sg[64 * SG_STRIDE];     // 17 KB staging

    const int a0  = blockIdx.x * 64;    // 70 blocks
    const int c0g = blockIdx.y * 128;   // 9 blocks (last: 1024..1151, tail padded)
    const int tid = threadIdx.x;

    if (blockIdx.y == 0) {
        float4* oz = (float4*)(out + (size_t)a0 * 64);
        #pragma unroll
        for (int t = 0; t < 4; t++)
            oz[tid + t * 256] = make_float4(0.f, 0.f, 0.f, 0.f);
    }

    // Fill Ah[r][j] (fp32 -> fp16), float4 loads
    #pragma unroll
    for (int t = 0; t < 4; t++) {
        int idx = tid + t * 256;
        int r = idx >> 4, f4 = idx & 15;
        float4 v = *(const float4*)(atom + (size_t)(a0 + r) * 64 + f4 * 4);
        __half2 h01 = __floats2half2_rn(v.x, v.y);
        __half2 h23 = __floats2half2_rn(v.z, v.w);
        *(uint2*)&Ah[r * AH_STRIDE + f4 * 4] =
            make_uint2(*(uint32_t*)&h01, *(uint32_t*)&h23);
    }
    // Fill Bs[c][j] = W[j][c0g+c]
    #pragma unroll
    for (int t = 0; t < 8; t++) {
        int idx = tid + t * 256;
        int c = idx >> 4, f4 = idx & 15;
        int gc = c0g + c;
        float4 v = make_float4(0.f, 0.f, 0.f, 0.f);
        if (gc < 1024) {
            int kk = gc >> 6, i = gc & 63;
            v = *(const float4*)(kern + kk * 4096 + i * 64 + f4 * 4);
        } else if (gc < 1088) {
            v = *(const float4*)(bias + (gc - 1024) * 64 + f4 * 4);
        }
        __half2 h01 = __floats2half2_rn(v.x, v.y);
        __half2 h23 = __floats2half2_rn(v.z, v.w);
        *(uint2*)&Bs[c * BS_STRIDE + f4 * 4] =
            make_uint2(*(uint32_t*)&h01, *(uint32_t*)&h23);
    }
    __syncthreads();

    const int wid  = tid >> 5;
    const int lane = tid & 31;
    const int m0   = (wid & 3) * 16;   // row group
    const int ch   = wid >> 2;         // col half (0 or 1)

    uint32_t Af[4][4];
    {
        const uint32_t a_base =
            smem_u32(&Ah[(m0 + (lane & 15)) * AH_STRIDE + ((lane >> 4) << 3)]);
        #pragma unroll
        for (int ks = 0; ks < 4; ks++)
            ldm_x4(Af[ks][0], Af[ks][1], Af[ks][2], Af[ks][3], a_base + ks * 32);
    }

    const uint32_t b_base =
        smem_u32(&Bs[(ch * 64 + ((lane >> 4) << 3) + (lane & 7)) * BS_STRIDE +
                     (((lane >> 3) & 1) << 3)]);

    float acc[8][4] = {};
    #pragma unroll
    for (int ks = 0; ks < 4; ks++) {
        #pragma unroll
        for (int nss = 0; nss < 4; nss++) {
            uint32_t B0, B1, B2, B3;
            ldm_x4(B0, B1, B2, B3,
                   b_base + nss * 16 * BS_STRIDE * 2 + ks * 32);
            mma16816(acc[2 * nss],     Af[ks][0], Af[ks][1], Af[ks][2], Af[ks][3], B0, B1);
            mma16816(acc[2 * nss + 1], Af[ks][0], Af[ks][1], Af[ks][2], Af[ks][3], B2, B3);
        }
    }

    // Stage accumulators in smem (local cols within this block's 128-col tile)
    const int r  = lane >> 2;
    const int cp = (lane & 3) * 2;
    #pragma unroll
    for (int s = 0; s < 8; s++) {
        const int lc = ch * 64 + s * 8 + cp;            // local col 0..127
        *(__half2*)&Sg[(m0 + r) * SG_STRIDE + lc]     = __floats2half2_rn(acc[s][0], acc[s][1]);
        *(__half2*)&Sg[(m0 + r + 8) * SG_STRIDE + lc] = __floats2half2_rn(acc[s][2], acc[s][3]);
    }
    __syncthreads();

    // Coalesced copy: 64 rows x 128 halves = 1024 uint4; 16 threads per row.
    #pragma unroll
    for (int t = 0; t < 4; t++) {
        int idx = tid + t * 256;
        int row = idx >> 4, ck = idx & 15;      // ck: 16B chunk (8 halves)
        uint4 v = *(const uint4*)&Sg[row * SG_STRIDE + ck * 8];
        *(uint4*)&g_Yh[(size_t)(a0 + row) * YSTRIDE + c0g + ck * 8] = v;
    }

    // PDL: allow the dependent edge_kernel to launch (Y writes for this block
    // are issued; visibility is enforced by the dependent's grid sync).
    __syncthreads();
    if (tid == 0) cudaTriggerProgrammaticLaunchCompletion();
}

// ---------------------------------------------------------------------------
// Phase 2: half-warp per edge (exact R12/R15 body — validated 13.5us).
// PDL: prefetch proj-independent lines into L2, then grid-dependency sync.
// ---------------------------------------------------------------------------
__global__ void __launch_bounds__(256)
edge_kernel(const float* __restrict__ bond,
            const int* __restrict__ pair,
            float* __restrict__ out)
{
    const int warp = blockIdx.x * 8 + (threadIdx.x >> 5);
    const int half = (threadIdx.x >> 4) & 1;
    const int lid  = threadIdx.x & 15;
    const int e = warp * 2 + half;

    // Prefetch this warp's bond rows (2 edges * 64B = one 128B line) and the
    // pair line into L2 while proj is still draining. Zero register cost.
    if ((threadIdx.x & 31) == 0) {
        const char* bpf = (const char*)(bond + (size_t)(warp * 2) * 16);
        asm volatile("prefetch.global.L2 [%0];" :: "l"(bpf));
        const char* ppf = (const char*)(pair + (size_t)(warp * 2) * 2);
        asm volatile("prefetch.global.L2 [%0];" :: "l"(ppf));
    }

    // Wait for proj's Y writes to be visible.
    cudaGridDependencySynchronize();

    const int2 pr = ((const int2*)pair)[e];
    const int dst = pr.x;
    const int src = pr.y;

    const float4* __restrict__ bp = (const float4*)(bond + (size_t)e * 16);
    const float4 q0 = __ldg(bp + 0);
    const float4 q1 = __ldg(bp + 1);
    const float4 q2 = __ldg(bp + 2);
    const float4 q3 = __ldg(bp + 3);
    const float bk[16] = {q0.x, q0.y, q0.z, q0.w,
                          q1.x, q1.y, q1.z, q1.w,
                          q2.x, q2.y, q2.z, q2.w,
                          q3.x, q3.y, q3.z, q3.w};

    const __half* __restrict__ y = g_Yh + (size_t)src * YSTRIDE + 4 * lid;

    float m0, m1, m2, m3;
    {
        const uint2 v = *(const uint2*)(y + 1024);
        const float2 flo = __half22float2(*(const __half2*)&v.x);
        const float2 fhi = __half22float2(*(const __half2*)&v.y);
        m0 = flo.x; m1 = flo.y; m2 = fhi.x; m3 = fhi.y;
    }

    #pragma unroll
    for (int k = 0; k < 16; k++) {
        const uint2 v = *(const uint2*)(y + k * 64);
        const float2 flo = __half22float2(*(const __half2*)&v.x);
        const float2 fhi = __half22float2(*(const __half2*)&v.y);
        const float b = bk[k];
        m0 = fmaf(b, flo.x, m0);
        m1 = fmaf(b, flo.y, m1);
        m2 = fmaf(b, fhi.x, m2);
        m3 = fmaf(b, fhi.y, m3);
    }

    float* o = out + (size_t)dst * 64 + 4 * lid;
    asm volatile("red.global.add.v4.f32 [%0], {%1, %2, %3, %4};"
                 :: "l"(o), "f"(m0), "f"(m1), "f"(m2), "f"(m3)
                 : "memory");
}

extern "C" void kernel_launch(void* const* d_in, const int* in_sizes, int n_in,
                              void* d_out, int out_size)
{
    const float* atom = (const float*)d_in[0];      // [4480, 64]
    const float* bond = (const float*)d_in[1];      // [65536, 16]
    const int*   pair = (const int*)d_in[2];        // [65536, 2] int32
    const float* kern = (const float*)d_in[3];      // [16, 4096]
    const float* bias = (const float*)d_in[4];      // [4096]
    float*       out  = (float*)d_out;              // [4480, 64]

    (void)in_sizes; (void)n_in; (void)out_size;

    dim3 grid1(NUM_SEGMENTS / 64, 9);  // (70, 9); y==0 blocks zero `out`
    proj_kernel<<<grid1, 256>>>(atom, kern, bias, out);

    // Edge kernel with programmatic dependent launch on the same stream.
    cudaLaunchConfig_t cfg = {};
    cfg.gridDim  = dim3(N_EDGES / 16);
    cfg.blockDim = dim3(256);
    cfg.dynamicSmemBytes = 0;
    cfg.stream = 0;
    cudaLaunchAttribute attrs[1];
    attrs[0].id = cudaLaunchAttributeProgrammaticStreamSerialization;
    attrs[0].val.programmaticStreamSerializationAllowed = 1;
    cfg.attrs = attrs;
    cfg.numAttrs = 1;
    cudaLaunchKernelEx(&cfg, edge_kernel, bond, pair, out);
}